// round 15
// baseline (speedup 1.0000x reference)
#include <cuda_runtime.h>
#include <cuda_bf16.h>
#include <cstdint>

// ---------------- problem constants ----------------
#define NNODES 100000
#define NEDGES 1600000
#define IND    128
#define HD     64
#define EDD    64
#define NLAYER 3
#define OUTD   3

#define TE     128            // edges per tile (MMA M)
#define ETHR   256            // 8 warps
#define NTHR   256
#define NTILES (NEDGES / TE)  // 12500
#define EGRID  152            // persistent CTAs (1/SM)

#define SA 68                 // A-tile row stride (floats)

// ---------------- device scratch ----------------
__device__ float g_h  [(size_t)NNODES * HD];
__device__ float g_agg[(size_t)NNODES * HD];
__device__ float g_ea [(size_t)NEDGES * EDD];
__device__ float g_pool[HD];
__device__ uint32_t g_wt[(size_t)NLAYER * 7 * 4096];  // tf32 weights, fragment-ordered

// ---------------- helpers ----------------
__device__ __forceinline__ uint32_t tf32b(float x) {
    uint32_t r;
    asm("cvt.rna.tf32.f32 %0, %1;" : "=r"(r) : "f"(x));
    return r;
}

#define MMA_TF32(c, a0, a1, a2, a3, b0, b1) \
    asm volatile("mma.sync.aligned.m16n8k8.row.col.f32.tf32.tf32.f32 " \
                 "{%0,%1,%2,%3}, {%4,%5,%6,%7}, {%8,%9}, {%0,%1,%2,%3};" \
                 : "+f"((c)[0]), "+f"((c)[1]), "+f"((c)[2]), "+f"((c)[3]) \
                 : "r"(a0), "r"(a1), "r"(a2), "r"(a3), "r"(b0), "r"(b1))

__device__ __forceinline__ void cp16(unsigned s, const void* g) {
    asm volatile("cp.async.cg.shared.global [%0], [%1], 16;" :: "r"(s), "l"(g));
}
#define CP_COMMIT() asm volatile("cp.async.commit_group;")
#define CP_WAIT0()  asm volatile("cp.async.wait_group 0;" ::: "memory")

__device__ __forceinline__ void red_v2(float* p, float a, float b) {
    asm volatile("red.global.add.v2.f32 [%0], {%1, %2};"
                 :: "l"(p), "f"(a), "f"(b) : "memory");
}

// ---------------- smem carve (float indices) ----------------
#define OFF_AH  0                    // h[row]         128*68 = 8704
#define OFF_AC  8704                 // h[col] -> EA'
#define OFF_AE  17408                // ea -> T -> T2
#define OFF_W   26112                // 7 chunks x 4096 u32 (fragment-ordered)
#define OFF_IDX 54784                // sCol: 128 ints
#define SMEM_EDGE_BYTES ((OFF_IDX + 128) * 4)   // 219,648 B

// ---------------- weight prep: tf32 + fragment-ordered layout ----------------
// u32 index in chunk = s*512 + h*256 + nbp*128 + lane*4 + j
__global__ void wt_kernel(const float* __restrict__ eW1, const float* __restrict__ eW2,
                          const float* __restrict__ nW1, const float* __restrict__ nW2) {
    int b = blockIdx.x;              // 0..20 : layer l, chunk c
    int l = b / 7, c = b % 7;
    const float* src;
    if (c < 3)       src = eW1 + ((size_t)l * 192 + c * 64) * 64;
    else if (c == 3) src = eW2 + (size_t)l * 64 * 64;
    else if (c < 6)  src = nW1 + ((size_t)l * 128 + (c - 4) * 64) * 64;
    else             src = nW2 + (size_t)l * 64 * 64;
    uint32_t* dst = g_wt + (size_t)b * 4096;
    for (int idx = threadIdx.x; idx < 4096; idx += NTHR) {
        int s   = idx >> 9;
        int h   = (idx >> 8) & 1;
        int nbp = (idx >> 7) & 1;
        int ln  = (idx >> 2) & 31;
        int j   = idx & 3;
        int g = ln >> 2, tg = ln & 3;
        int nb = 2 * nbp + (j >> 1);
        int kk = 8 * s + tg + ((j & 1) ? 4 : 0);
        int n  = 32 * h + 8 * nb + g;
        dst[idx] = tf32b(src[kk * 64 + n]);
    }
}

// ---------------- fused edge-layer kernel (persistent, mma.sync tf32) ----------------
// Warp w (8 warps): edges [(w&3)*32, +32) (2 m-tiles), n-half h=(w>>2) -> n in [32h,+32)
__device__ __forceinline__ void kloop8(const uint32_t* __restrict__ aw,
                                       const uint4* __restrict__ wq,
                                       int g, int tg, int hofs, int lane,
                                       float acc[2][4][4]) {
#pragma unroll
    for (int s = 0; s < 8; s++) {
        uint32_t a00 = aw[g * SA + 8 * s + tg];
        uint32_t a01 = aw[(g + 8) * SA + 8 * s + tg];
        uint32_t a02 = aw[g * SA + 8 * s + tg + 4];
        uint32_t a03 = aw[(g + 8) * SA + 8 * s + tg + 4];
        uint32_t a10 = aw[(g + 16) * SA + 8 * s + tg];
        uint32_t a11 = aw[(g + 24) * SA + 8 * s + tg];
        uint32_t a12 = aw[(g + 16) * SA + 8 * s + tg + 4];
        uint32_t a13 = aw[(g + 24) * SA + 8 * s + tg + 4];
        uint4 q0 = wq[s * 128 + hofs + lane];
        uint4 q1 = wq[s * 128 + hofs + 32 + lane];
        MMA_TF32(acc[0][0], a00, a01, a02, a03, q0.x, q0.y);
        MMA_TF32(acc[0][1], a00, a01, a02, a03, q0.z, q0.w);
        MMA_TF32(acc[0][2], a00, a01, a02, a03, q1.x, q1.y);
        MMA_TF32(acc[0][3], a00, a01, a02, a03, q1.z, q1.w);
        MMA_TF32(acc[1][0], a10, a11, a12, a13, q0.x, q0.y);
        MMA_TF32(acc[1][1], a10, a11, a12, a13, q0.z, q0.w);
        MMA_TF32(acc[1][2], a10, a11, a12, a13, q1.x, q1.y);
        MMA_TF32(acc[1][3], a10, a11, a12, a13, q1.z, q1.w);
    }
}

template <bool RELU>
__device__ __forceinline__ void epi_store(float acc[2][4][4], uint32_t* __restrict__ dst,
                                          int eb, int g, int tg, int nbase,
                                          const float* __restrict__ bias) {
#pragma unroll
    for (int mt = 0; mt < 2; mt++)
#pragma unroll
        for (int nb = 0; nb < 4; nb++) {
            int col = nbase + nb * 8 + 2 * tg;
            float b0 = __ldg(bias + col), b1 = __ldg(bias + col + 1);
            float v00 = acc[mt][nb][0] + b0, v01 = acc[mt][nb][1] + b1;
            float v10 = acc[mt][nb][2] + b0, v11 = acc[mt][nb][3] + b1;
            if (RELU) {
                v00 = fmaxf(v00, 0.f); v01 = fmaxf(v01, 0.f);
                v10 = fmaxf(v10, 0.f); v11 = fmaxf(v11, 0.f);
            }
            int row = eb + mt * 16 + g;
            *(uint2*)(dst + row * SA + col)       = make_uint2(tf32b(v00), tf32b(v01));
            *(uint2*)(dst + (row + 8) * SA + col) = make_uint2(tf32b(v10), tf32b(v11));
        }
}

__device__ __forceinline__ void init_acc(float acc[2][4][4]) {
#pragma unroll
    for (int mt = 0; mt < 2; mt++)
#pragma unroll
        for (int nb = 0; nb < 4; nb++)
#pragma unroll
            for (int i = 0; i < 4; i++) acc[mt][nb][i] = 0.f;
}

__global__ void __launch_bounds__(ETHR, 1)
edge_kernel(const int* __restrict__ ei, const float* __restrict__ ea_in,
            const uint32_t* __restrict__ wt,
            const float* __restrict__ B1b, const float* __restrict__ B2b,
            const float* __restrict__ B3b, const float* __restrict__ B4b,
            int write_ea) {
    extern __shared__ float sm[];
    uint32_t* tAH = (uint32_t*)(sm + OFF_AH);
    uint32_t* tAC = (uint32_t*)(sm + OFF_AC);
    uint32_t* tAE = (uint32_t*)(sm + OFF_AE);
    const uint4* Wq = (const uint4*)(sm + OFF_W);
    int* sCol = (int*)(sm + OFF_IDX);

    unsigned sbase;
    asm("{ .reg .u64 t; cvta.to.shared.u64 t, %1; cvt.u32.u64 %0, t; }"
        : "=r"(sbase) : "l"((const void*)sm));
    const unsigned wds = sbase + OFF_W * 4u;

    const int tid  = threadIdx.x;
    const int lane = tid & 31;
    const int wid  = tid >> 5;
    const int g    = lane >> 2;
    const int tg   = lane & 3;
    const int eb   = (wid & 3) * 32;       // warp's 32-edge base
    const int h    = wid >> 2;             // n-half
    const int nbase = h * 32;
    const int hofs  = h * 64;

    // stage ALL 7 weight chunks ONCE per CTA (7168 uint4 = 28 x 256)
    {
        const float4* gw = (const float4*)wt;
#pragma unroll
        for (int i = 0; i < 28; i++)
            cp16(wds + (unsigned)(tid + i * ETHR) * 16u, gw + tid + i * ETHR);
        CP_COMMIT();
        CP_WAIT0();
    }
    __syncthreads();

    const uint32_t* awH = tAH + eb * SA;
    const uint32_t* awC = tAC + eb * SA;
    const uint32_t* awE = tAE + eb * SA;
#define WC(c) (Wq + (c) * 1024)

    const int ge = tid >> 1, gq = tid & 1;   // gather: 2 threads/edge, 32 floats each

    for (int t = blockIdx.x; t < NTILES; t += EGRID) {
        const long long e0 = (long long)t * TE;

        __syncthreads();                     // (0) previous iteration drained

        // gathers: tf32-truncate on store
        {
            int r = ei[e0 + ge];
            int c = ei[(long long)NEDGES + e0 + ge];
            if (gq == 0) sCol[ge] = c;
            const float4* hr = (const float4*)(g_h + (size_t)r * HD) + gq * 8;
            const float4* hc = (const float4*)(g_h + (size_t)c * HD) + gq * 8;
            const float4* ee = (const float4*)(ea_in + (size_t)(e0 + ge) * EDD) + gq * 8;
#pragma unroll
            for (int j = 0; j < 8; j++) {
                float4 v = hr[j];
                *(uint4*)(tAH + ge * SA + gq * 32 + 4 * j) =
                    make_uint4(tf32b(v.x), tf32b(v.y), tf32b(v.z), tf32b(v.w));
                v = hc[j];
                *(uint4*)(tAC + ge * SA + gq * 32 + 4 * j) =
                    make_uint4(tf32b(v.x), tf32b(v.y), tf32b(v.z), tf32b(v.w));
                v = ee[j];
                *(uint4*)(tAE + ge * SA + gq * 32 + 4 * j) =
                    make_uint4(tf32b(v.x), tf32b(v.y), tf32b(v.z), tf32b(v.w));
            }
        }
        __syncthreads();                     // (1) gathers visible

        float acc[2][4][4];

        // ---- GEMM1: [hrow|hcol|ea] @ W1 (+relu,b1) -> tAE ----
        init_acc(acc);
        kloop8(awH, WC(0), g, tg, hofs, lane, acc);
        kloop8(awC, WC(1), g, tg, hofs, lane, acc);
        kloop8(awE, WC(2), g, tg, hofs, lane, acc);
        __syncthreads();                     // (2) all tAE reads done
        epi_store<true>(acc, tAE, eb, g, tg, nbase, B1b);
        __syncthreads();                     // (3) T visible

        // ---- GEMM2: T @ W2 (+b2) -> tAC (EA') ----
        init_acc(acc);
        kloop8(awE, WC(3), g, tg, hofs, lane, acc);
        epi_store<false>(acc, tAC, eb, g, tg, nbase, B2b);   // tAC reads ended before (2)
        __syncthreads();                     // (4) EA' visible

        // persist EA' (coalesced via smem rows)
        if (write_ea) {
            float4* dst = (float4*)(g_ea + (size_t)(e0 + ge) * EDD + gq * 32);
            const uint32_t* srcr = tAC + ge * SA + gq * 32;
#pragma unroll
            for (int j = 0; j < 8; j++) dst[j] = *(const float4*)(srcr + 4 * j);
        }

        // ---- GEMM3: [hrow|EA'] @ W3 (+relu,b3) -> tAE ----
        init_acc(acc);
        kloop8(awH, WC(4), g, tg, hofs, lane, acc);
        kloop8(awC, WC(5), g, tg, hofs, lane, acc);
        epi_store<true>(acc, tAE, eb, g, tg, nbase, B3b);    // tAE reads ended before (4)
        __syncthreads();                     // (5) T2 visible

        // ---- GEMM4: T2 @ W4 (+b4) -> scatter-add ----
        init_acc(acc);
        kloop8(awE, WC(6), g, tg, hofs, lane, acc);

#pragma unroll
        for (int mt = 0; mt < 2; mt++) {
            int c_lo = sCol[eb + mt * 16 + g];
            int c_hi = sCol[eb + mt * 16 + g + 8];
            float* p_lo = g_agg + (size_t)c_lo * HD;
            float* p_hi = g_agg + (size_t)c_hi * HD;
#pragma unroll
            for (int nb = 0; nb < 4; nb++) {
                int col = nbase + nb * 8 + 2 * tg;
                float b0 = __ldg(B4b + col), b1 = __ldg(B4b + col + 1);
                red_v2(p_lo + col, acc[mt][nb][0] + b0, acc[mt][nb][1] + b1);
                red_v2(p_hi + col, acc[mt][nb][2] + b0, acc[mt][nb][3] + b1);
            }
        }
    }
}

// ---------------- tiny alignment kernel (keeps ncu sample on an edge launch) ----
__global__ void nudge_kernel() {
    if (threadIdx.x < HD) g_pool[threadIdx.x] = 0.f;
}

// ---------------- node projection: h = x @ pW + pb ; agg = 0 ----------------
#define SMEM_PROJ_FLOATS (32 * 132 + 128 * 64)
#define SMEM_PROJ_BYTES  (SMEM_PROJ_FLOATS * 4)

__global__ void __launch_bounds__(NTHR, 1)
proj_kernel(const float* __restrict__ x, const float* __restrict__ pW,
            const float* __restrict__ pb) {
    extern __shared__ float sm[];
    float* xs  = sm;            // [32][132]
    float* sWp = sm + 32 * 132; // [128][64]
    int tid = threadIdx.x;
    int nb0 = blockIdx.x * 32;

    {
        const float4* gx = (const float4*)(x + (size_t)nb0 * IND);
        for (int i = tid; i < 1024; i += NTHR) {
            float4 vv = gx[i];
            *(float4*)(xs + (i >> 5) * 132 + ((i & 31) << 2)) = vv;
        }
    }
    {
        const float4* gw = (const float4*)pW;
        float4* sw = (float4*)sWp;
        for (int i = tid; i < 2048; i += NTHR) sw[i] = gw[i];
    }
    __syncthreads();

    int node = tid >> 3, g = tid & 7;
    float a0[8];
    float4 b0 = *(const float4*)(pb + 8 * g);
    float4 b1 = *(const float4*)(pb + 8 * g + 4);
    a0[0] = b0.x; a0[1] = b0.y; a0[2] = b0.z; a0[3] = b0.w;
    a0[4] = b1.x; a0[5] = b1.y; a0[6] = b1.z; a0[7] = b1.w;
#pragma unroll 4
    for (int k = 0; k < IND; k++) {
        float a = xs[node * 132 + k];
        float4 w0 = *(const float4*)(sWp + k * 64 + 8 * g);
        float4 w1 = *(const float4*)(sWp + k * 64 + 8 * g + 4);
        a0[0] = fmaf(a, w0.x, a0[0]); a0[1] = fmaf(a, w0.y, a0[1]);
        a0[2] = fmaf(a, w0.z, a0[2]); a0[3] = fmaf(a, w0.w, a0[3]);
        a0[4] = fmaf(a, w1.x, a0[4]); a0[5] = fmaf(a, w1.y, a0[5]);
        a0[6] = fmaf(a, w1.z, a0[6]); a0[7] = fmaf(a, w1.w, a0[7]);
    }
    size_t base = (size_t)(nb0 + node) * HD + 8 * g;
    *(float4*)(g_h + base)     = make_float4(a0[0], a0[1], a0[2], a0[3]);
    *(float4*)(g_h + base + 4) = make_float4(a0[4], a0[5], a0[6], a0[7]);
    *(float4*)(g_agg + base)     = make_float4(0.f, 0.f, 0.f, 0.f);
    *(float4*)(g_agg + base + 4) = make_float4(0.f, 0.f, 0.f, 0.f);
}

// ---------------- node update: h = relu(agg + h); agg = 0; zero g_pool --------
__global__ void node_update_kernel() {
    size_t i = (size_t)blockIdx.x * NTHR + threadIdx.x;  // float4 index
    float4* h4 = (float4*)g_h;
    float4* a4 = (float4*)g_agg;
    float4 h = h4[i], a = a4[i];
    h.x = fmaxf(h.x + a.x, 0.f);
    h.y = fmaxf(h.y + a.y, 0.f);
    h.z = fmaxf(h.z + a.z, 0.f);
    h.w = fmaxf(h.w + a.w, 0.f);
    h4[i] = h;
    a4[i] = make_float4(0.f, 0.f, 0.f, 0.f);
    if (blockIdx.x == 0 && threadIdx.x < HD) g_pool[threadIdx.x] = 0.f;
}

// ---------------- pooling ----------------
__global__ void pool_kernel() {
    __shared__ float sP[NTHR];
    int tid = threadIdx.x;
    int k = tid & 63, sub = tid >> 6;
    int n0 = blockIdx.x * 256 + sub * 64;
    float s = 0.f;
#pragma unroll 4
    for (int i = 0; i < 64; i++) {
        int n = n0 + i;
        if (n < NNODES) s += g_h[(size_t)n * HD + k];
    }
    sP[tid] = s;
    __syncthreads();
    if (tid < 64) {
        float t = sP[tid] + sP[tid + 64] + sP[tid + 128] + sP[tid + 192];
        atomicAdd(&g_pool[tid], t);
    }
}

// ---------------- final ----------------
__global__ void final_kernel(const float* __restrict__ lW, const float* __restrict__ lb,
                             float* __restrict__ out) {
    int o = threadIdx.x;
    if (o < OUTD) {
        const float invN = 1.0f / (float)NNODES;
        float s = lb[o];
        for (int k = 0; k < HD; k++) s = fmaf(g_pool[k] * invN, lW[k * OUTD + o], s);
        out[o] = s;
    }
}

// ---------------- launch ----------------
extern "C" void kernel_launch(void* const* d_in, const int* in_sizes, int n_in,
                              void* d_out, int out_size) {
    const float* x   = (const float*)d_in[0];
    const int*   ei  = (const int*)d_in[1];       // int32 (JAX x64 disabled)
    const float* ea  = (const float*)d_in[2];
    const float* pW  = (const float*)d_in[3];
    const float* pb  = (const float*)d_in[4];
    const float* eW1 = (const float*)d_in[5];
    const float* eb1 = (const float*)d_in[6];
    const float* eW2 = (const float*)d_in[7];
    const float* eb2 = (const float*)d_in[8];
    const float* nW1 = (const float*)d_in[9];
    const float* nb1 = (const float*)d_in[10];
    const float* nW2 = (const float*)d_in[11];
    const float* nb2 = (const float*)d_in[12];
    const float* lW  = (const float*)d_in[13];
    const float* lb  = (const float*)d_in[14];
    float* out = (float*)d_out;

    cudaFuncSetAttribute(edge_kernel, cudaFuncAttributeMaxDynamicSharedMemorySize, SMEM_EDGE_BYTES);
    cudaFuncSetAttribute(proj_kernel, cudaFuncAttributeMaxDynamicSharedMemorySize, SMEM_PROJ_BYTES);

    float*    g_ea_ptr;  cudaGetSymbolAddress((void**)&g_ea_ptr, g_ea);
    uint32_t* g_wt_ptr;  cudaGetSymbolAddress((void**)&g_wt_ptr, g_wt);

    // launch order: wt(1) proj(2) nudge(3) edge0(4) nu(5) edge1(6 <- ncu -s 5)
    wt_kernel<<<NLAYER * 7, NTHR>>>(eW1, eW2, nW1, nW2);
    proj_kernel<<<NNODES / 32, NTHR, SMEM_PROJ_BYTES>>>(x, pW, pb);
    nudge_kernel<<<1, 64>>>();

    for (int l = 0; l < NLAYER; l++) {
        const float* ea_in = (l == 0) ? ea : (const float*)g_ea_ptr;
        edge_kernel<<<EGRID, ETHR, SMEM_EDGE_BYTES>>>(
            ei, ea_in,
            g_wt_ptr + (size_t)l * 7 * 4096,
            eb1 + l * 64, eb2 + l * 64, nb1 + l * 64, nb2 + l * 64,
            (l < NLAYER - 1) ? 1 : 0);
        node_update_kernel<<<(NNODES * HD) / (4 * NTHR), NTHR>>>();
    }

    pool_kernel<<<(NNODES + 255) / 256, NTHR>>>();
    final_kernel<<<1, 32>>>(lW, lb, out);
}

// round 17
// speedup vs baseline: 1.5974x; 1.5974x over previous
#include <cuda_runtime.h>
#include <cuda_bf16.h>
#include <cstdint>

// ---------------- problem constants ----------------
#define NNODES 100000
#define NEDGES 1600000
#define IND    128
#define HD     64
#define EDD    64
#define NLAYER 3
#define OUTD   3

#define TE     128            // edges per tile (MMA M)
#define ETHR   256            // 8 warps per CTA, 2 CTAs/SM
#define NTHR   256
#define NTILES (NEDGES / TE)  // 12500
#define EGRID  304            // 2 per SM

#define SAH 72                // A-tile row stride (half units; 144 B)

// ---------------- device scratch ----------------
__device__ float    g_h  [(size_t)NNODES * HD];     // node features (fp32: protects residual)
__device__ float    g_agg[(size_t)NNODES * HD];     // scatter accumulator (fp32)
__device__ uint16_t g_ea16[(size_t)NEDGES * EDD];   // edge features between layers (fp16)
__device__ float    g_pool[HD];
__device__ uint32_t g_wt [(size_t)NLAYER * 7 * 2048];  // fp16 weights, fragment-ordered

// ---------------- helpers ----------------
// pack two fp32 -> f16x2 (lo in low 16 bits)
#define F16X2(d, lo, hi) \
    asm("cvt.rn.f16x2.f32 %0, %1, %2;" : "=r"(d) : "f"(hi), "f"(lo))

#define MMA_F16(c, a0, a1, a2, a3, b0, b1) \
    asm volatile("mma.sync.aligned.m16n8k16.row.col.f32.f16.f16.f32 " \
                 "{%0,%1,%2,%3}, {%4,%5,%6,%7}, {%8,%9}, {%0,%1,%2,%3};" \
                 : "+f"((c)[0]), "+f"((c)[1]), "+f"((c)[2]), "+f"((c)[3]) \
                 : "r"(a0), "r"(a1), "r"(a2), "r"(a3), "r"(b0), "r"(b1))

__device__ __forceinline__ void cp16(unsigned s, const void* g) {
    asm volatile("cp.async.cg.shared.global [%0], [%1], 16;" :: "r"(s), "l"(g));
}
#define CP_COMMIT() asm volatile("cp.async.commit_group;")
#define CP_WAIT0()  asm volatile("cp.async.wait_group 0;" ::: "memory")

__device__ __forceinline__ void red_v2(float* p, float a, float b) {
    asm volatile("red.global.add.v2.f32 [%0], {%1, %2};"
                 :: "l"(p), "f"(a), "f"(b) : "memory");
}

// ---------------- smem carve (byte offsets) ----------------
// A tiles: 128 rows x 72 half (144 B/row) = 18,432 B each
#define OFF_AH  0
#define OFF_AC  18432
#define OFF_AE  36864
#define OFF_W   55296      // 7 chunks x 8192 B (fp16 fragment-ordered)
#define OFF_IDX 112640     // sCol: 128 ints
#define SMEM_EDGE_BYTES (112640 + 512)   // 113,152 B -> 2 CTAs/SM

// ---------------- weight prep: fp16 + fragment-ordered layout ----------------
// chunk = 64k x 64n, stored as 2048 u32:
//   idx = s*512 + h*256 + nbp*128 + lane*4 + j   (s: k16-step 0..3)
//   lane = 4g+tg; nb = 2*nbp + (j>>1); k0 = 16s + 2tg + ((j&1)?8:0); n = 32h + 8nb + g
//   val = f16x2(W[k0][n], W[k0+1][n])
__global__ void wt_kernel(const float* __restrict__ eW1, const float* __restrict__ eW2,
                          const float* __restrict__ nW1, const float* __restrict__ nW2) {
    int b = blockIdx.x;              // 0..20 : layer l, chunk c
    int l = b / 7, c = b % 7;
    const float* src;
    if (c < 3)       src = eW1 + ((size_t)l * 192 + c * 64) * 64;
    else if (c == 3) src = eW2 + (size_t)l * 64 * 64;
    else if (c < 6)  src = nW1 + ((size_t)l * 128 + (c - 4) * 64) * 64;
    else             src = nW2 + (size_t)l * 64 * 64;
    uint32_t* dst = g_wt + (size_t)b * 2048;
    for (int idx = threadIdx.x; idx < 2048; idx += NTHR) {
        int s   = idx >> 9;
        int h   = (idx >> 8) & 1;
        int nbp = (idx >> 7) & 1;
        int ln  = (idx >> 2) & 31;
        int j   = idx & 3;
        int g = ln >> 2, tg = ln & 3;
        int nb = 2 * nbp + (j >> 1);
        int k0 = 16 * s + 2 * tg + ((j & 1) ? 8 : 0);
        int n  = 32 * h + 8 * nb + g;
        uint32_t v;
        F16X2(v, src[k0 * 64 + n], src[(k0 + 1) * 64 + n]);
        dst[idx] = v;
    }
}

// ---------------- fused edge-layer kernel (persistent, mma.sync fp16) ----------------
// 8 warps: 4 edge-groups (32 edges, M=32) x 2 n-halves (32 cols)
// one 64-k chunk = 4 k16-steps, 8 MMAs/step
__device__ __forceinline__ void kloop4(const uint16_t* __restrict__ aw,
                                       const uint4* __restrict__ wq,
                                       int g, int tg, int hsel /*h*64*/, int lane,
                                       float acc[2][4][4]) {
#pragma unroll
    for (int s = 0; s < 4; s++) {
        int ks = 16 * s + 2 * tg;
        uint32_t a00 = *(const uint32_t*)(aw + (g)      * SAH + ks);
        uint32_t a01 = *(const uint32_t*)(aw + (g + 8)  * SAH + ks);
        uint32_t a02 = *(const uint32_t*)(aw + (g)      * SAH + ks + 8);
        uint32_t a03 = *(const uint32_t*)(aw + (g + 8)  * SAH + ks + 8);
        uint32_t a10 = *(const uint32_t*)(aw + (g + 16) * SAH + ks);
        uint32_t a11 = *(const uint32_t*)(aw + (g + 24) * SAH + ks);
        uint32_t a12 = *(const uint32_t*)(aw + (g + 16) * SAH + ks + 8);
        uint32_t a13 = *(const uint32_t*)(aw + (g + 24) * SAH + ks + 8);
        uint4 q0 = wq[s * 128 + hsel + lane];
        uint4 q1 = wq[s * 128 + hsel + 32 + lane];
        MMA_F16(acc[0][0], a00, a01, a02, a03, q0.x, q0.y);
        MMA_F16(acc[0][1], a00, a01, a02, a03, q0.z, q0.w);
        MMA_F16(acc[0][2], a00, a01, a02, a03, q1.x, q1.y);
        MMA_F16(acc[0][3], a00, a01, a02, a03, q1.z, q1.w);
        MMA_F16(acc[1][0], a10, a11, a12, a13, q0.x, q0.y);
        MMA_F16(acc[1][1], a10, a11, a12, a13, q0.z, q0.w);
        MMA_F16(acc[1][2], a10, a11, a12, a13, q1.x, q1.y);
        MMA_F16(acc[1][3], a10, a11, a12, a13, q1.z, q1.w);
    }
}

template <bool RELU>
__device__ __forceinline__ void epi_store(float acc[2][4][4], uint16_t* __restrict__ dst,
                                          int eb, int g, int tg, int nbase,
                                          const float* __restrict__ bias) {
#pragma unroll
    for (int mt = 0; mt < 2; mt++)
#pragma unroll
        for (int nb = 0; nb < 4; nb++) {
            int col = nbase + nb * 8 + 2 * tg;
            float b0 = __ldg(bias + col), b1 = __ldg(bias + col + 1);
            float v00 = acc[mt][nb][0] + b0, v01 = acc[mt][nb][1] + b1;
            float v10 = acc[mt][nb][2] + b0, v11 = acc[mt][nb][3] + b1;
            if (RELU) {
                v00 = fmaxf(v00, 0.f); v01 = fmaxf(v01, 0.f);
                v10 = fmaxf(v10, 0.f); v11 = fmaxf(v11, 0.f);
            }
            uint32_t p0, p1;
            F16X2(p0, v00, v01);
            F16X2(p1, v10, v11);
            int row = eb + mt * 16 + g;
            *(uint32_t*)(dst + row * SAH + col)       = p0;
            *(uint32_t*)(dst + (row + 8) * SAH + col) = p1;
        }
}

__device__ __forceinline__ void init_acc(float acc[2][4][4]) {
#pragma unroll
    for (int mt = 0; mt < 2; mt++)
#pragma unroll
        for (int nb = 0; nb < 4; nb++)
#pragma unroll
            for (int i = 0; i < 4; i++) acc[mt][nb][i] = 0.f;
}

// gather 32 fp32 -> 16 f16x2 -> 4 STS.128 into row at half-offset 32q
__device__ __forceinline__ void gather_f32(const float* __restrict__ src,
                                           uint16_t* __restrict__ dstrow) {
    uint32_t buf[16];
    const float4* s4 = (const float4*)src;
#pragma unroll
    for (int j = 0; j < 8; j++) {
        float4 v = s4[j];
        F16X2(buf[2 * j],     v.x, v.y);
        F16X2(buf[2 * j + 1], v.z, v.w);
    }
    uint4* d = (uint4*)dstrow;
#pragma unroll
    for (int k = 0; k < 4; k++) d[k] = ((uint4*)buf)[k];
}

__global__ void __launch_bounds__(ETHR, 2)
edge_kernel(const int* __restrict__ ei, const float* __restrict__ ea_f32,
            const uint32_t* __restrict__ wt,
            const float* __restrict__ B1b, const float* __restrict__ B2b,
            const float* __restrict__ B3b, const float* __restrict__ B4b,
            int ea_is_f16, int write_ea) {
    extern __shared__ char smc[];
    uint16_t* tAH = (uint16_t*)(smc + OFF_AH);
    uint16_t* tAC = (uint16_t*)(smc + OFF_AC);
    uint16_t* tAE = (uint16_t*)(smc + OFF_AE);
    const uint4* Wq = (const uint4*)(smc + OFF_W);
    int* sCol = (int*)(smc + OFF_IDX);

    unsigned sbase;
    asm("{ .reg .u64 t; cvta.to.shared.u64 t, %1; cvt.u32.u64 %0, t; }"
        : "=r"(sbase) : "l"((const void*)smc));

    const int tid  = threadIdx.x;
    const int lane = tid & 31;
    const int wid  = tid >> 5;
    const int g    = lane >> 2;
    const int tg   = lane & 3;
    const int eb   = (wid & 3) * 32;       // warp's 32-edge base
    const int h    = wid >> 2;             // n-half
    const int nbase = h * 32;
    const int hsel  = h * 64;

    // stage ALL 7 fp16 weight chunks ONCE per CTA (3584 uint4 = 14 x 256)
    {
        const float4* gw = (const float4*)wt;
#pragma unroll
        for (int i = 0; i < 14; i++)
            cp16(sbase + OFF_W + (unsigned)(tid + i * ETHR) * 16u, gw + tid + i * ETHR);
        CP_COMMIT();
        CP_WAIT0();
    }
    __syncthreads();

    const uint16_t* awH = tAH + eb * SAH;
    const uint16_t* awC = tAC + eb * SAH;
    const uint16_t* awE = tAE + eb * SAH;
#define WC(c) (Wq + (c) * 512)

    const int ge = tid >> 1, gq = tid & 1;   // gather: 2 threads/edge, 32 cols each

    for (int t = blockIdx.x; t < NTILES; t += EGRID) {
        const long long e0 = (long long)t * TE;

        __syncthreads();                     // (0) previous iteration drained

        // gathers
        {
            int r = ei[e0 + ge];
            int c = ei[(long long)NEDGES + e0 + ge];
            if (gq == 0) sCol[ge] = c;
            gather_f32(g_h + (size_t)r * HD + 32 * gq, tAH + ge * SAH + 32 * gq);
            gather_f32(g_h + (size_t)c * HD + 32 * gq, tAC + ge * SAH + 32 * gq);
            if (ea_is_f16) {
                const uint4* es = (const uint4*)(g_ea16 + (size_t)(e0 + ge) * EDD + 32 * gq);
                uint4* ed = (uint4*)(tAE + ge * SAH + 32 * gq);
#pragma unroll
                for (int k = 0; k < 4; k++) ed[k] = es[k];
            } else {
                gather_f32(ea_f32 + (size_t)(e0 + ge) * EDD + 32 * gq,
                           tAE + ge * SAH + 32 * gq);
            }
        }
        __syncthreads();                     // (1) gathers visible

        float acc[2][4][4];

        // ---- GEMM1: [hrow|hcol|ea] @ W1 (+relu,b1) -> tAE ----
        init_acc(acc);
        kloop4(awH, WC(0), g, tg, hsel, lane, acc);
        kloop4(awC, WC(1), g, tg, hsel, lane, acc);
        kloop4(awE, WC(2), g, tg, hsel, lane, acc);
        __syncthreads();                     // (2) all tAE reads done
        epi_store<true>(acc, tAE, eb, g, tg, nbase, B1b);
        __syncthreads();                     // (3) T visible

        // ---- GEMM2: T @ W2 (+b2) -> tAC (EA') ----
        init_acc(acc);
        kloop4(awE, WC(3), g, tg, hsel, lane, acc);
        epi_store<false>(acc, tAC, eb, g, tg, nbase, B2b);   // tAC reads ended before (2)
        __syncthreads();                     // (4) EA' visible

        // persist EA' as fp16 (coalesced)
        if (write_ea) {
            const uint4* srcr = (const uint4*)(tAC + ge * SAH + 32 * gq);
            uint4* dst = (uint4*)(g_ea16 + (size_t)(e0 + ge) * EDD + 32 * gq);
#pragma unroll
            for (int k = 0; k < 4; k++) dst[k] = srcr[k];
        }

        // ---- GEMM3: [hrow|EA'] @ W3 (+relu,b3) -> tAE ----
        init_acc(acc);
        kloop4(awH, WC(4), g, tg, hsel, lane, acc);
        kloop4(awC, WC(5), g, tg, hsel, lane, acc);
        epi_store<true>(acc, tAE, eb, g, tg, nbase, B3b);    // tAE reads ended before (4)
        __syncthreads();                     // (5) T2 visible

        // ---- GEMM4: T2 @ W4 (+b4) -> scatter-add ----
        init_acc(acc);
        kloop4(awE, WC(6), g, tg, hsel, lane, acc);

#pragma unroll
        for (int mt = 0; mt < 2; mt++) {
            int c_lo = sCol[eb + mt * 16 + g];
            int c_hi = sCol[eb + mt * 16 + g + 8];
            float* p_lo = g_agg + (size_t)c_lo * HD;
            float* p_hi = g_agg + (size_t)c_hi * HD;
#pragma unroll
            for (int nb = 0; nb < 4; nb++) {
                int col = nbase + nb * 8 + 2 * tg;
                float b0 = __ldg(B4b + col), b1 = __ldg(B4b + col + 1);
                red_v2(p_lo + col, acc[mt][nb][0] + b0, acc[mt][nb][1] + b1);
                red_v2(p_hi + col, acc[mt][nb][2] + b0, acc[mt][nb][3] + b1);
            }
        }
    }
}

// ---------------- tiny alignment kernel (keeps ncu sample on an edge launch) ----
__global__ void nudge_kernel() {
    if (threadIdx.x < HD) g_pool[threadIdx.x] = 0.f;
}

// ---------------- node projection: h = x @ pW + pb ; agg = 0 ----------------
#define SMEM_PROJ_FLOATS (32 * 132 + 128 * 64)
#define SMEM_PROJ_BYTES  (SMEM_PROJ_FLOATS * 4)

__global__ void __launch_bounds__(NTHR, 1)
proj_kernel(const float* __restrict__ x, const float* __restrict__ pW,
            const float* __restrict__ pb) {
    extern __shared__ float sm[];
    float* xs  = sm;            // [32][132]
    float* sWp = sm + 32 * 132; // [128][64]
    int tid = threadIdx.x;
    int nb0 = blockIdx.x * 32;

    {
        const float4* gx = (const float4*)(x + (size_t)nb0 * IND);
        for (int i = tid; i < 1024; i += NTHR) {
            float4 vv = gx[i];
            *(float4*)(xs + (i >> 5) * 132 + ((i & 31) << 2)) = vv;
        }
    }
    {
        const float4* gw = (const float4*)pW;
        float4* sw = (float4*)sWp;
        for (int i = tid; i < 2048; i += NTHR) sw[i] = gw[i];
    }
    __syncthreads();

    int node = tid >> 3, g = tid & 7;
    float a0[8];
    float4 b0 = *(const float4*)(pb + 8 * g);
    float4 b1 = *(const float4*)(pb + 8 * g + 4);
    a0[0] = b0.x; a0[1] = b0.y; a0[2] = b0.z; a0[3] = b0.w;
    a0[4] = b1.x; a0[5] = b1.y; a0[6] = b1.z; a0[7] = b1.w;
#pragma unroll 4
    for (int k = 0; k < IND; k++) {
        float a = xs[node * 132 + k];
        float4 w0 = *(const float4*)(sWp + k * 64 + 8 * g);
        float4 w1 = *(const float4*)(sWp + k * 64 + 8 * g + 4);
        a0[0] = fmaf(a, w0.x, a0[0]); a0[1] = fmaf(a, w0.y, a0[1]);
        a0[2] = fmaf(a, w0.z, a0[2]); a0[3] = fmaf(a, w0.w, a0[3]);
        a0[4] = fmaf(a, w1.x, a0[4]); a0[5] = fmaf(a, w1.y, a0[5]);
        a0[6] = fmaf(a, w1.z, a0[6]); a0[7] = fmaf(a, w1.w, a0[7]);
    }
    size_t base = (size_t)(nb0 + node) * HD + 8 * g;
    *(float4*)(g_h + base)     = make_float4(a0[0], a0[1], a0[2], a0[3]);
    *(float4*)(g_h + base + 4) = make_float4(a0[4], a0[5], a0[6], a0[7]);
    *(float4*)(g_agg + base)     = make_float4(0.f, 0.f, 0.f, 0.f);
    *(float4*)(g_agg + base + 4) = make_float4(0.f, 0.f, 0.f, 0.f);
}

// ---------------- node update: h = relu(agg + h); agg = 0; zero g_pool --------
__global__ void node_update_kernel() {
    size_t i = (size_t)blockIdx.x * NTHR + threadIdx.x;  // float4 index
    float4* h4 = (float4*)g_h;
    float4* a4 = (float4*)g_agg;
    float4 h = h4[i], a = a4[i];
    h.x = fmaxf(h.x + a.x, 0.f);
    h.y = fmaxf(h.y + a.y, 0.f);
    h.z = fmaxf(h.z + a.z, 0.f);
    h.w = fmaxf(h.w + a.w, 0.f);
    h4[i] = h;
    a4[i] = make_float4(0.f, 0.f, 0.f, 0.f);
    if (blockIdx.x == 0 && threadIdx.x < HD) g_pool[threadIdx.x] = 0.f;
}

// ---------------- pooling ----------------
__global__ void pool_kernel() {
    __shared__ float sP[NTHR];
    int tid = threadIdx.x;
    int k = tid & 63, sub = tid >> 6;
    int n0 = blockIdx.x * 256 + sub * 64;
    float s = 0.f;
#pragma unroll 4
    for (int i = 0; i < 64; i++) {
        int n = n0 + i;
        if (n < NNODES) s += g_h[(size_t)n * HD + k];
    }
    sP[tid] = s;
    __syncthreads();
    if (tid < 64) {
        float t = sP[tid] + sP[tid + 64] + sP[tid + 128] + sP[tid + 192];
        atomicAdd(&g_pool[tid], t);
    }
}

// ---------------- final ----------------
__global__ void final_kernel(const float* __restrict__ lW, const float* __restrict__ lb,
                             float* __restrict__ out) {
    int o = threadIdx.x;
    if (o < OUTD) {
        const float invN = 1.0f / (float)NNODES;
        float s = lb[o];
        for (int k = 0; k < HD; k++) s = fmaf(g_pool[k] * invN, lW[k * OUTD + o], s);
        out[o] = s;
    }
}

// ---------------- launch ----------------
extern "C" void kernel_launch(void* const* d_in, const int* in_sizes, int n_in,
                              void* d_out, int out_size) {
    const float* x   = (const float*)d_in[0];
    const int*   ei  = (const int*)d_in[1];       // int32 (JAX x64 disabled)
    const float* ea  = (const float*)d_in[2];
    const float* pW  = (const float*)d_in[3];
    const float* pb  = (const float*)d_in[4];
    const float* eW1 = (const float*)d_in[5];
    const float* eb1 = (const float*)d_in[6];
    const float* eW2 = (const float*)d_in[7];
    const float* eb2 = (const float*)d_in[8];
    const float* nW1 = (const float*)d_in[9];
    const float* nb1 = (const float*)d_in[10];
    const float* nW2 = (const float*)d_in[11];
    const float* nb2 = (const float*)d_in[12];
    const float* lW  = (const float*)d_in[13];
    const float* lb  = (const float*)d_in[14];
    float* out = (float*)d_out;

    cudaFuncSetAttribute(edge_kernel, cudaFuncAttributeMaxDynamicSharedMemorySize, SMEM_EDGE_BYTES);
    cudaFuncSetAttribute(proj_kernel, cudaFuncAttributeMaxDynamicSharedMemorySize, SMEM_PROJ_BYTES);

    uint32_t* g_wt_ptr;  cudaGetSymbolAddress((void**)&g_wt_ptr, g_wt);

    // launch order: wt(1) proj(2) nudge(3) edge0(4) nu(5) edge1(6 <- ncu -s 5)
    wt_kernel<<<NLAYER * 7, NTHR>>>(eW1, eW2, nW1, nW2);
    proj_kernel<<<NNODES / 32, NTHR, SMEM_PROJ_BYTES>>>(x, pW, pb);
    nudge_kernel<<<1, 64>>>();

    for (int l = 0; l < NLAYER; l++) {
        edge_kernel<<<EGRID, ETHR, SMEM_EDGE_BYTES>>>(
            ei, ea,
            g_wt_ptr + (size_t)l * 7 * 2048,
            eb1 + l * 64, eb2 + l * 64, nb1 + l * 64, nb2 + l * 64,
            (l > 0) ? 1 : 0,               // ea input is fp16 after layer 0
            (l < NLAYER - 1) ? 1 : 0);
        node_update_kernel<<<(NNODES * HD) / (4 * NTHR), NTHR>>>();
    }

    pool_kernel<<<(NNODES + 255) / 256, NTHR>>>();
    final_kernel<<<1, 32>>>(lW, lb, out);
}